// round 16
// baseline (speedup 1.0000x reference)
#include <cuda_runtime.h>
#include <cuda_bf16.h>
#include <cstdint>

#define N_ROWS 4096
#define DIM    512
#define VWORDS 50000
#define KNN    10
#define EPS    2.0f

#define TM 128
#define TN 128
#define KC 64                     /* bf16 k per chunk */
#define NCHUNK (DIM / KC)         /* 8 */
#define RTILES (N_ROWS / TM)      /* 32 */
#define CTILES 391                /* 391*128 = 50048 >= 50000 */

#define VSPLIT 64
#define VCHUNK 782
#define ASLOTS 16
#define PREP_BLOCKS (VWORDS / 8)  /* 6250 */

// ---------------------------------------------------------------------------
// PTX helpers (compute_103-safe subset: cp.async, ldmatrix, mma.sync bf16)
// ---------------------------------------------------------------------------
__device__ __forceinline__ uint32_t smem_to_u32(const void* p) {
    uint32_t a;
    asm("{ .reg .u64 t; cvta.to.shared.u64 t, %1; cvt.u32.u64 %0, t; }" : "=r"(a) : "l"(p));
    return a;
}
#define CP_ASYNC16(dst, src) \
    asm volatile("cp.async.cg.shared.global [%0], [%1], 16;" :: "r"(dst), "l"(src) : "memory")
#define CP_COMMIT() asm volatile("cp.async.commit_group;" ::: "memory")
#define CP_WAIT1()  asm volatile("cp.async.wait_group 1;" ::: "memory")
#define CP_WAIT0()  asm volatile("cp.async.wait_group 0;" ::: "memory")

#define LDSM_X4(r, addr) \
    asm volatile("ldmatrix.sync.aligned.m8n8.x4.shared.b16 {%0,%1,%2,%3}, [%4];" \
        : "=r"((r)[0]), "=r"((r)[1]), "=r"((r)[2]), "=r"((r)[3]) : "r"(addr))

#define MMA16816(d, a, b) \
    asm volatile("mma.sync.aligned.m16n8k16.row.col.f32.bf16.bf16.f32 " \
        "{%0,%1,%2,%3}, {%4,%5,%6,%7}, {%8,%9}, {%0,%1,%2,%3};" \
        : "+f"((d)[0]), "+f"((d)[1]), "+f"((d)[2]), "+f"((d)[3]) \
        : "r"((a)[0]), "r"((a)[1]), "r"((a)[2]), "r"((a)[3]), "r"((b)[0]), "r"((b)[1]))

#define SWZ(off) ((off) ^ (((off) >> 3) & 0x70))

// ---------------------------------------------------------------------------
// Scratch (device globals; no allocations)
// ---------------------------------------------------------------------------
__device__ float          g_w2[VWORDS];
__device__ float          g_st[N_ROWS];
__device__ int            g_tgt[N_ROWS];
__device__ int            g_rowlist[N_ROWS];
__device__ int            g_clo[N_ROWS];
__device__ int            g_chi[N_ROWS];
__device__ int            g_amb[N_ROWS];
__device__ int            g_exc[N_ROWS];
__device__ int            g_rowdone[RTILES];
__device__ __nv_bfloat16  g_x1[N_ROWS * DIM];         // compacted bf16 X
__device__ __nv_bfloat16  g_wb[(size_t)VWORDS * DIM]; // 51.2 MB, bf16 W
__device__ int            g_nm;
__device__ int            g_namb;
__device__ int            g_hits;
__device__ int            g_done;

// ---------------------------------------------------------------------------
// K1 (fused): blocks [0, PREP_BLOCKS): W prep — 8 words/block, 1 warp/word,
// MLP=4, shuffle-only reduction; counter zeroing.
// Blocks [PREP_BLOCKS, +N_ROWS): target rows (w2[t] inline — no dependency).
__global__ void k_prep(const float* __restrict__ W, const float* __restrict__ X,
                       const long long* __restrict__ tgt, const int* __restrict__ mask) {
    const int bid = blockIdx.x;
    const int tid = threadIdx.x;

    if (bid >= PREP_BLOCKS) {
        // ---- target path ----
        int n = bid - PREP_BLOCKS;
        if (mask[n] == 0) return;
        __shared__ float red[4], red2[4];
        __shared__ int slot;
        int t = (int)tgt[n];
        float4 a = make_float4(0.f, 0.f, 0.f, 0.f);
        if (tid < 128) {
            a = reinterpret_cast<const float4*>(X + (size_t)n * DIM)[tid];
            float4 b = reinterpret_cast<const float4*>(W + (size_t)t * DIM)[tid];
            float s  = a.x * b.x + a.y * b.y + a.z * b.z + a.w * b.w;
            float s2 = b.x * b.x + b.y * b.y + b.z * b.z + b.w * b.w;
#pragma unroll
            for (int o = 16; o; o >>= 1) {
                s  += __shfl_down_sync(0xffffffffu, s,  o);
                s2 += __shfl_down_sync(0xffffffffu, s2, o);
            }
            if ((tid & 31) == 0) { red[tid >> 5] = s; red2[tid >> 5] = s2; }
        }
        __syncthreads();
        if (tid == 0) {
            float dot = red[0] + red[1] + red[2] + red[3];
            float w2t = red2[0] + red2[1] + red2[2] + red2[3];
            int i = atomicAdd(&g_nm, 1);
            slot = i;
            g_st[i] = w2t - 2.0f * dot;
            g_tgt[i] = t;
            g_rowlist[i] = n;
        }
        __syncthreads();
        if (tid < 128) {
            int i = slot;
            __nv_bfloat162 p0 = __floats2bfloat162_rn(a.x, a.y);
            __nv_bfloat162 p1 = __floats2bfloat162_rn(a.z, a.w);
            uint2 val;
            val.x = *reinterpret_cast<uint32_t*>(&p0);
            val.y = *reinterpret_cast<uint32_t*>(&p1);
            *reinterpret_cast<uint2*>(g_x1 + (size_t)i * DIM + tid * 4) = val;
        }
        return;
    }

    // ---- prep path: 1 warp per word, MLP=4 ----
    int zi = bid * blockDim.x + tid;
    if (zi < N_ROWS) { g_clo[zi] = 0; g_chi[zi] = 0; g_exc[zi] = 0; }
    if (zi < RTILES) g_rowdone[zi] = 0;
    if (zi == 0) { g_nm = 0; g_namb = 0; g_hits = 0; g_done = 0; }

    const int v = bid * 8 + (tid >> 5);
    const int lane = tid & 31;
    const float4* wr = reinterpret_cast<const float4*>(W + (size_t)v * DIM);
    float4 x0 = wr[lane];
    float4 x1 = wr[lane + 32];
    float4 x2 = wr[lane + 64];
    float4 x3 = wr[lane + 96];

    __nv_bfloat16* dst = g_wb + (size_t)v * DIM;
#define CVT_STORE(xx, off)                                                     \
    {                                                                          \
        __nv_bfloat162 p0 = __floats2bfloat162_rn((xx).x, (xx).y);             \
        __nv_bfloat162 p1 = __floats2bfloat162_rn((xx).z, (xx).w);             \
        uint2 val;                                                             \
        val.x = *reinterpret_cast<uint32_t*>(&p0);                             \
        val.y = *reinterpret_cast<uint32_t*>(&p1);                             \
        *reinterpret_cast<uint2*>(dst + (off) * 4) = val;                      \
    }
    CVT_STORE(x0, lane);
    CVT_STORE(x1, lane + 32);
    CVT_STORE(x2, lane + 64);
    CVT_STORE(x3, lane + 96);
#undef CVT_STORE

    float s = x0.x * x0.x + x0.y * x0.y + x0.z * x0.z + x0.w * x0.w
            + x1.x * x1.x + x1.y * x1.y + x1.z * x1.z + x1.w * x1.w
            + x2.x * x2.x + x2.y * x2.y + x2.z * x2.z + x2.w * x2.w
            + x3.x * x3.x + x3.y * x3.y + x3.z * x3.z + x3.w * x3.w;
#pragma unroll
    for (int o = 16; o; o >>= 1) s += __shfl_down_sync(0xffffffffu, s, o);
    if (lane == 0) g_w2[v] = s;
}

// ---------------------------------------------------------------------------
// K2: bf16 HMMA screening GEMM, 128x128 tile, 8 warps of 32x64,
// 3-stage cp.async, hoisted addressing, one sync per chunk. (R10-proven)
// Classification fused via per-row-tile ticket: last col-tile CTA classifies.
#define STAGE_BYTES 32768
#define NSTAGE 3
#define SM_TOTAL (NSTAGE * STAGE_BYTES)

__global__ __launch_bounds__(256, 2) void k_mma() {
    const int nm = g_nm;
    const int row0 = blockIdx.x * TM;
    if (row0 >= nm) return;
    const int col0 = blockIdx.y * TN;

    extern __shared__ char smem[];
    const uint32_t sbase = smem_to_u32(smem);
    __shared__ float w2s[TN];
    __shared__ int slo[TM], shi[TM];

    const int tid = threadIdx.x;
    const int lane = tid & 31;
    const int wid = tid >> 5;
    const int wm = wid & 3;     // 4 M groups of 32
    const int wn = wid >> 2;    // 2 N groups of 64

    if (tid < TN) {
        int v = col0 + tid;
        w2s[tid] = (v < VWORDS) ? g_w2[v] : 0.0f;
    }
    if (tid < TM) { slo[tid] = 0; shi[tid] = 0; }

    // hoisted cp.async addressing (clamped; garbage lanes masked in epilogue)
    const char* baseA = (const char*)g_x1;
    const char* baseB = (const char*)g_wb;
    uint32_t offA[4], offB[4];
    const int rb = tid >> 3, qb = (tid & 7) * 16;
#pragma unroll
    for (int it = 0; it < 4; it++) {
        int gr = row0 + rb + it * 32;
        int grc = gr < nm ? gr : 0;
        offA[it] = (uint32_t)grc * (DIM * 2) + qb;
        int v = col0 + rb + it * 32;
        int vc = v < VWORDS ? v : VWORDS - 1;
        offB[it] = (uint32_t)vc * (DIM * 2) + qb;
    }
    const uint32_t d0 = SWZ((uint32_t)(rb * 128 + qb));

    float acc[2][8][4];
#pragma unroll
    for (int i = 0; i < 2; i++)
#pragma unroll
        for (int j = 0; j < 8; j++)
#pragma unroll
            for (int f = 0; f < 4; f++) acc[i][j][f] = 0.0f;

#define ISSUE_LOAD(st, koff)                                                  \
    do {                                                                      \
        uint32_t _ab = sbase + (st) * STAGE_BYTES;                            \
        _Pragma("unroll")                                                     \
        for (int _it = 0; _it < 4; _it++)                                     \
            CP_ASYNC16(_ab + d0 + _it * 4096, baseA + offA[_it] + (koff));    \
        _Pragma("unroll")                                                     \
        for (int _it = 0; _it < 4; _it++)                                     \
            CP_ASYNC16(_ab + 16384 + d0 + _it * 4096, baseB + offB[_it] + (koff)); \
        CP_COMMIT();                                                          \
    } while (0)

    ISSUE_LOAD(0, 0);
    ISSUE_LOAD(1, KC * 2);

#pragma unroll
    for (int c = 0; c < NCHUNK; c++) {
        if (c < NCHUNK - 1) CP_WAIT1(); else CP_WAIT0();
        __syncthreads();
        if (c + 2 < NCHUNK) ISSUE_LOAD((c + 2) % NSTAGE, (c + 2) * KC * 2);

        const uint32_t A = sbase + (c % NSTAGE) * STAGE_BYTES;
        const uint32_t B = A + 16384;
#pragma unroll
        for (int ks = 0; ks < KC / 16; ks++) {
            uint32_t a[2][4];
#pragma unroll
            for (int i = 0; i < 2; i++) {
                int row = wm * 32 + i * 16 + (lane & 15);
                int colg = ks * 2 + (lane >> 4);
                uint32_t byte = (uint32_t)(row * 128 + colg * 16);
                LDSM_X4(a[i], A + SWZ(byte));
            }
            uint32_t b[8][2];
#pragma unroll
            for (int p = 0; p < 4; p++) {
                int row = wn * 64 + p * 16 + (lane & 15);
                int colg = ks * 2 + (lane >> 4);
                uint32_t byte = (uint32_t)(row * 128 + colg * 16);
                uint32_t r4[4];
                LDSM_X4(r4, B + SWZ(byte));
                b[2 * p + 0][0] = r4[0]; b[2 * p + 1][0] = r4[1];
                b[2 * p + 0][1] = r4[2]; b[2 * p + 1][1] = r4[3];
            }
#pragma unroll
            for (int i = 0; i < 2; i++)
#pragma unroll
                for (int j = 0; j < 8; j++)
                    MMA16816(acc[i][j], a[i], b[j]);
        }
        // no trailing sync: next iteration's wait+sync orders stage reuse
    }
#undef ISSUE_LOAD

    __syncthreads();

    // --- epilogue: margin counting ---
#pragma unroll
    for (int i = 0; i < 2; i++) {
#pragma unroll
        for (int h = 0; h < 2; h++) {
            int rloc = wm * 32 + i * 16 + h * 8 + (lane >> 2);
            int gi = row0 + rloc;
            bool valid = gi < nm;
            float st = valid ? g_st[gi] : 0.0f;
            int t = valid ? g_tgt[gi] : -1;
            float stl = st - EPS, sth = st + EPS;
            int clo = 0, chi = 0;
#pragma unroll
            for (int j = 0; j < 8; j++) {
#pragma unroll
                for (int e = 0; e < 2; e++) {
                    int cl = wn * 64 + j * 8 + (lane & 3) * 2 + e;
                    int v = col0 + cl;
                    float s = w2s[cl] - 2.0f * acc[i][j][h * 2 + e];
                    int ok = (v < VWORDS) & (v != t);
                    clo += ok & (s < stl);
                    chi += ok & (s <= sth);
                }
            }
            clo += __shfl_xor_sync(0xffffffffu, clo, 1);
            clo += __shfl_xor_sync(0xffffffffu, clo, 2);
            chi += __shfl_xor_sync(0xffffffffu, chi, 1);
            chi += __shfl_xor_sync(0xffffffffu, chi, 2);
            if ((lane & 3) == 0 && valid) {
                if (clo) atomicAdd(&slo[rloc], clo);
                if (chi) atomicAdd(&shi[rloc], chi);
            }
        }
    }
    __syncthreads();
    if (tid < TM) {
        int gi = row0 + tid;
        if (gi < nm) {
            if (slo[tid]) atomicAdd(&g_clo[gi], slo[tid]);
            if (shi[tid]) atomicAdd(&g_chi[gi], shi[tid]);
        }
        __threadfence();   // make this thread's clo/chi updates visible before ticket
    }
    __syncthreads();

    // --- fused classification: last col-tile CTA for this row tile ---
    __shared__ int lastTicket;
    if (tid == 0)
        lastTicket = atomicAdd(&g_rowdone[blockIdx.x], 1);
    __syncthreads();
    if (lastTicket == CTILES - 1) {
        __threadfence();
        if (tid < TM) {
            int gi = row0 + tid;
            if (gi < nm) {
                int clo = g_clo[gi], chi = g_chi[gi];
                if (clo < KNN) {
                    if (chi < KNN) {
                        atomicAdd(&g_hits, 1);
                    } else {
                        int p = atomicAdd(&g_namb, 1);
                        g_amb[p] = gi;
                    }
                }
            }
        }
    }
}

// ---------------------------------------------------------------------------
// K3 (fused): exact f32 recount for ambiguous rows (early-exit via g_amb list)
//             + last-block final reduction (ticket pattern, small grid).
__global__ __launch_bounds__(256) void k_exact(const float* __restrict__ X,
                                               const float* __restrict__ W,
                                               float* __restrict__ out) {
    const int namb = g_namb;
    const int v0 = blockIdx.x * VCHUNK;
    const int v1 = min(v0 + VCHUNK, VWORDS);
    const int lane = threadIdx.x & 31;
    const int warp = threadIdx.x >> 5;

    for (int ai = blockIdx.y; ai < namb; ai += ASLOTS) {
        const int i = g_amb[ai];
        const int n = g_rowlist[i], t = g_tgt[i];
        const float st = g_st[i];
        const float4* xr = reinterpret_cast<const float4*>(X + (size_t)n * DIM);
        float4 x0 = xr[lane], x1 = xr[lane + 32], x2 = xr[lane + 64], x3 = xr[lane + 96];
        int cnt = 0;
        for (int v = v0 + warp; v < v1; v += 8) {
            const float4* wr = reinterpret_cast<const float4*>(W + (size_t)v * DIM);
            float4 w0 = wr[lane], w1 = wr[lane + 32], w2v = wr[lane + 64], w3 = wr[lane + 96];
            float p = x0.x * w0.x + x0.y * w0.y + x0.z * w0.z + x0.w * w0.w;
            p += x1.x * w1.x + x1.y * w1.y + x1.z * w1.z + x1.w * w1.w;
            p += x2.x * w2v.x + x2.y * w2v.y + x2.z * w2v.z + x2.w * w2v.w;
            p += x3.x * w3.x + x3.y * w3.y + x3.z * w3.z + x3.w * w3.w;
#pragma unroll
            for (int o = 16; o; o >>= 1) p += __shfl_down_sync(0xffffffffu, p, o);
            if (lane == 0 && v != t) {
                float s = g_w2[v] - 2.0f * p;
                cnt += (s < st) || (s == st && v < t);
            }
        }
        if (lane == 0 && cnt) atomicAdd(&g_exc[ai], cnt);
    }

    // ---- last-block finalize (scans only namb elements) ----
    __threadfence();
    __shared__ int isLast;
    if (threadIdx.x == 0) {
        int tk = atomicAdd(&g_done, 1);
        isLast = (tk == VSPLIT * ASLOTS - 1);
    }
    __syncthreads();
    if (!isLast) return;
    __threadfence();

    float s = 0.0f;
    for (int ai = threadIdx.x; ai < namb; ai += 256)
        s += (g_exc[ai] < KNN) ? 1.0f : 0.0f;
#pragma unroll
    for (int o = 16; o; o >>= 1) s += __shfl_down_sync(0xffffffffu, s, o);
    __shared__ float red[8];
    if ((threadIdx.x & 31) == 0) red[threadIdx.x >> 5] = s;
    __syncthreads();
    if (threadIdx.x == 0) {
        float tot = (float)g_hits;
#pragma unroll
        for (int i = 0; i < 8; i++) tot += red[i];
        int nm = g_nm;
        out[0] = (nm > 0) ? (tot / (float)nm) : 0.0f;
    }
}

// ---------------------------------------------------------------------------
extern "C" void kernel_launch(void* const* d_in, const int* in_sizes, int n_in,
                              void* d_out, int out_size) {
    const float*     logits = (const float*)d_in[0];
    const long long* target = (const long long*)d_in[1];
    const int*       mask   = (const int*)d_in[2];
    const float*     W      = (const float*)d_in[3];

    cudaFuncSetAttribute(k_mma, cudaFuncAttributeMaxDynamicSharedMemorySize, SM_TOTAL);

    k_prep<<<PREP_BLOCKS + N_ROWS, 256>>>(W, logits, target, mask);
    k_mma<<<dim3(RTILES, CTILES), 256, SM_TOTAL>>>();
    k_exact<<<dim3(VSPLIT, ASLOTS), 256>>>(logits, W, (float*)d_out);
}

// round 17
// speedup vs baseline: 1.2210x; 1.2210x over previous
#include <cuda_runtime.h>
#include <cuda_bf16.h>
#include <cstdint>

#define N_ROWS 4096
#define DIM    512
#define VWORDS 50000
#define KNN    10
#define EPS    2.0f

#define TM 128
#define TN 128
#define KC 64                     /* bf16 k per chunk */
#define NCHUNK (DIM / KC)         /* 8 */
#define RTILES (N_ROWS / TM)      /* 32 */
#define CTILES 391                /* 391*128 = 50048 >= 50000 */

#define VSPLIT 64
#define VCHUNK 782
#define ASLOTS 16
#define PREP_BLOCKS (VWORDS / 8)  /* 6250 */

// ---------------------------------------------------------------------------
// PTX helpers (compute_103-safe subset: cp.async, ldmatrix, mma.sync bf16)
// ---------------------------------------------------------------------------
__device__ __forceinline__ uint32_t smem_to_u32(const void* p) {
    uint32_t a;
    asm("{ .reg .u64 t; cvta.to.shared.u64 t, %1; cvt.u32.u64 %0, t; }" : "=r"(a) : "l"(p));
    return a;
}
#define CP_ASYNC16(dst, src) \
    asm volatile("cp.async.cg.shared.global [%0], [%1], 16;" :: "r"(dst), "l"(src) : "memory")
#define CP_COMMIT() asm volatile("cp.async.commit_group;" ::: "memory")
#define CP_WAIT1()  asm volatile("cp.async.wait_group 1;" ::: "memory")
#define CP_WAIT0()  asm volatile("cp.async.wait_group 0;" ::: "memory")

#define LDSM_X4(r, addr) \
    asm volatile("ldmatrix.sync.aligned.m8n8.x4.shared.b16 {%0,%1,%2,%3}, [%4];" \
        : "=r"((r)[0]), "=r"((r)[1]), "=r"((r)[2]), "=r"((r)[3]) : "r"(addr))

#define MMA16816(d, a, b) \
    asm volatile("mma.sync.aligned.m16n8k16.row.col.f32.bf16.bf16.f32 " \
        "{%0,%1,%2,%3}, {%4,%5,%6,%7}, {%8,%9}, {%0,%1,%2,%3};" \
        : "+f"((d)[0]), "+f"((d)[1]), "+f"((d)[2]), "+f"((d)[3]) \
        : "r"((a)[0]), "r"((a)[1]), "r"((a)[2]), "r"((a)[3]), "r"((b)[0]), "r"((b)[1]))

#define SWZ(off) ((off) ^ (((off) >> 3) & 0x70))

// ---------------------------------------------------------------------------
// Scratch (device globals; no allocations)
// ---------------------------------------------------------------------------
__device__ float          g_w2[VWORDS];
__device__ float          g_st[N_ROWS];
__device__ int            g_tgt[N_ROWS];
__device__ int            g_rowlist[N_ROWS];
__device__ int            g_clo[N_ROWS];
__device__ int            g_chi[N_ROWS];
__device__ int            g_amb[N_ROWS];
__device__ int            g_exc[N_ROWS];
__device__ __nv_bfloat16  g_x1[N_ROWS * DIM];         // compacted bf16 X
__device__ __nv_bfloat16  g_wb[(size_t)VWORDS * DIM]; // 51.2 MB, bf16 W
__device__ int            g_nm;
__device__ int            g_namb;
__device__ int            g_hits;
__device__ int            g_done;

// ---------------------------------------------------------------------------
// K1 (fused): blocks [0, PREP_BLOCKS): W prep — 8 words/block, 1 warp/word,
// 4 float4 loads per thread (MLP=4), shuffle-only reduction; counter zeroing.
// Blocks [PREP_BLOCKS, +N_ROWS): target rows (w2[t] inline — no dependency).
__global__ void k_prep(const float* __restrict__ W, const float* __restrict__ X,
                       const long long* __restrict__ tgt, const int* __restrict__ mask) {
    const int bid = blockIdx.x;
    const int tid = threadIdx.x;

    if (bid >= PREP_BLOCKS) {
        // ---- target path ----
        int n = bid - PREP_BLOCKS;
        if (mask[n] == 0) return;
        __shared__ float red[4], red2[4];
        __shared__ int slot;
        int t = (int)tgt[n];
        float4 a = make_float4(0.f, 0.f, 0.f, 0.f);
        if (tid < 128) {
            a = reinterpret_cast<const float4*>(X + (size_t)n * DIM)[tid];
            float4 b = reinterpret_cast<const float4*>(W + (size_t)t * DIM)[tid];
            float s  = a.x * b.x + a.y * b.y + a.z * b.z + a.w * b.w;
            float s2 = b.x * b.x + b.y * b.y + b.z * b.z + b.w * b.w;
#pragma unroll
            for (int o = 16; o; o >>= 1) {
                s  += __shfl_down_sync(0xffffffffu, s,  o);
                s2 += __shfl_down_sync(0xffffffffu, s2, o);
            }
            if ((tid & 31) == 0) { red[tid >> 5] = s; red2[tid >> 5] = s2; }
        }
        __syncthreads();
        if (tid == 0) {
            float dot = red[0] + red[1] + red[2] + red[3];
            float w2t = red2[0] + red2[1] + red2[2] + red2[3];
            int i = atomicAdd(&g_nm, 1);
            slot = i;
            g_st[i] = w2t - 2.0f * dot;
            g_tgt[i] = t;
            g_rowlist[i] = n;
        }
        __syncthreads();
        if (tid < 128) {
            int i = slot;
            __nv_bfloat162 p0 = __floats2bfloat162_rn(a.x, a.y);
            __nv_bfloat162 p1 = __floats2bfloat162_rn(a.z, a.w);
            uint2 val;
            val.x = *reinterpret_cast<uint32_t*>(&p0);
            val.y = *reinterpret_cast<uint32_t*>(&p1);
            *reinterpret_cast<uint2*>(g_x1 + (size_t)i * DIM + tid * 4) = val;
        }
        return;
    }

    // ---- prep path: 1 warp per word, MLP=4 ----
    int zi = bid * blockDim.x + tid;
    if (zi < N_ROWS) { g_clo[zi] = 0; g_chi[zi] = 0; g_exc[zi] = 0; }
    if (zi == 0) { g_nm = 0; g_namb = 0; g_hits = 0; g_done = 0; }

    const int v = bid * 8 + (tid >> 5);
    const int lane = tid & 31;
    const float4* wr = reinterpret_cast<const float4*>(W + (size_t)v * DIM);
    float4 x0 = wr[lane];
    float4 x1 = wr[lane + 32];
    float4 x2 = wr[lane + 64];
    float4 x3 = wr[lane + 96];

    __nv_bfloat16* dst = g_wb + (size_t)v * DIM;
#define CVT_STORE(xx, off)                                                     \
    {                                                                          \
        __nv_bfloat162 p0 = __floats2bfloat162_rn((xx).x, (xx).y);             \
        __nv_bfloat162 p1 = __floats2bfloat162_rn((xx).z, (xx).w);             \
        uint2 val;                                                             \
        val.x = *reinterpret_cast<uint32_t*>(&p0);                             \
        val.y = *reinterpret_cast<uint32_t*>(&p1);                             \
        *reinterpret_cast<uint2*>(dst + (off) * 4) = val;                      \
    }
    CVT_STORE(x0, lane);
    CVT_STORE(x1, lane + 32);
    CVT_STORE(x2, lane + 64);
    CVT_STORE(x3, lane + 96);
#undef CVT_STORE

    float s = x0.x * x0.x + x0.y * x0.y + x0.z * x0.z + x0.w * x0.w
            + x1.x * x1.x + x1.y * x1.y + x1.z * x1.z + x1.w * x1.w
            + x2.x * x2.x + x2.y * x2.y + x2.z * x2.z + x2.w * x2.w
            + x3.x * x3.x + x3.y * x3.y + x3.z * x3.z + x3.w * x3.w;
#pragma unroll
    for (int o = 16; o; o >>= 1) s += __shfl_down_sync(0xffffffffu, s, o);
    if (lane == 0) g_w2[v] = s;
}

// ---------------------------------------------------------------------------
// K2: bf16 HMMA screening GEMM, 128x128 tile, 8 warps of 32x64,
// 3-stage cp.async, hoisted addressing, one sync per chunk. (R10-proven)
#define STAGE_BYTES 32768
#define NSTAGE 3
#define SM_TOTAL (NSTAGE * STAGE_BYTES)

__global__ __launch_bounds__(256, 2) void k_mma() {
    const int nm = g_nm;
    const int row0 = blockIdx.x * TM;
    if (row0 >= nm) return;
    const int col0 = blockIdx.y * TN;

    extern __shared__ char smem[];
    const uint32_t sbase = smem_to_u32(smem);
    __shared__ float w2s[TN];
    __shared__ int slo[TM], shi[TM];

    const int tid = threadIdx.x;
    const int lane = tid & 31;
    const int wid = tid >> 5;
    const int wm = wid & 3;     // 4 M groups of 32
    const int wn = wid >> 2;    // 2 N groups of 64

    if (tid < TN) {
        int v = col0 + tid;
        w2s[tid] = (v < VWORDS) ? g_w2[v] : 0.0f;
    }
    if (tid < TM) { slo[tid] = 0; shi[tid] = 0; }

    // hoisted cp.async addressing (clamped; garbage lanes masked in epilogue)
    const char* baseA = (const char*)g_x1;
    const char* baseB = (const char*)g_wb;
    uint32_t offA[4], offB[4];
    const int rb = tid >> 3, qb = (tid & 7) * 16;
#pragma unroll
    for (int it = 0; it < 4; it++) {
        int gr = row0 + rb + it * 32;
        int grc = gr < nm ? gr : 0;
        offA[it] = (uint32_t)grc * (DIM * 2) + qb;
        int v = col0 + rb + it * 32;
        int vc = v < VWORDS ? v : VWORDS - 1;
        offB[it] = (uint32_t)vc * (DIM * 2) + qb;
    }
    const uint32_t d0 = SWZ((uint32_t)(rb * 128 + qb));

    float acc[2][8][4];
#pragma unroll
    for (int i = 0; i < 2; i++)
#pragma unroll
        for (int j = 0; j < 8; j++)
#pragma unroll
            for (int f = 0; f < 4; f++) acc[i][j][f] = 0.0f;

#define ISSUE_LOAD(st, koff)                                                  \
    do {                                                                      \
        uint32_t _ab = sbase + (st) * STAGE_BYTES;                            \
        _Pragma("unroll")                                                     \
        for (int _it = 0; _it < 4; _it++)                                     \
            CP_ASYNC16(_ab + d0 + _it * 4096, baseA + offA[_it] + (koff));    \
        _Pragma("unroll")                                                     \
        for (int _it = 0; _it < 4; _it++)                                     \
            CP_ASYNC16(_ab + 16384 + d0 + _it * 4096, baseB + offB[_it] + (koff)); \
        CP_COMMIT();                                                          \
    } while (0)

    ISSUE_LOAD(0, 0);
    ISSUE_LOAD(1, KC * 2);

#pragma unroll
    for (int c = 0; c < NCHUNK; c++) {
        if (c < NCHUNK - 1) CP_WAIT1(); else CP_WAIT0();
        __syncthreads();
        if (c + 2 < NCHUNK) ISSUE_LOAD((c + 2) % NSTAGE, (c + 2) * KC * 2);

        const uint32_t A = sbase + (c % NSTAGE) * STAGE_BYTES;
        const uint32_t B = A + 16384;
#pragma unroll
        for (int ks = 0; ks < KC / 16; ks++) {
            uint32_t a[2][4];
#pragma unroll
            for (int i = 0; i < 2; i++) {
                int row = wm * 32 + i * 16 + (lane & 15);
                int colg = ks * 2 + (lane >> 4);
                uint32_t byte = (uint32_t)(row * 128 + colg * 16);
                LDSM_X4(a[i], A + SWZ(byte));
            }
            uint32_t b[8][2];
#pragma unroll
            for (int p = 0; p < 4; p++) {
                int row = wn * 64 + p * 16 + (lane & 15);
                int colg = ks * 2 + (lane >> 4);
                uint32_t byte = (uint32_t)(row * 128 + colg * 16);
                uint32_t r4[4];
                LDSM_X4(r4, B + SWZ(byte));
                b[2 * p + 0][0] = r4[0]; b[2 * p + 1][0] = r4[1];
                b[2 * p + 0][1] = r4[2]; b[2 * p + 1][1] = r4[3];
            }
#pragma unroll
            for (int i = 0; i < 2; i++)
#pragma unroll
                for (int j = 0; j < 8; j++)
                    MMA16816(acc[i][j], a[i], b[j]);
        }
        // no trailing sync: next iteration's wait+sync orders stage reuse
    }
#undef ISSUE_LOAD

    __syncthreads();

    // --- epilogue: margin counting ---
#pragma unroll
    for (int i = 0; i < 2; i++) {
#pragma unroll
        for (int h = 0; h < 2; h++) {
            int rloc = wm * 32 + i * 16 + h * 8 + (lane >> 2);
            int gi = row0 + rloc;
            bool valid = gi < nm;
            float st = valid ? g_st[gi] : 0.0f;
            int t = valid ? g_tgt[gi] : -1;
            float stl = st - EPS, sth = st + EPS;
            int clo = 0, chi = 0;
#pragma unroll
            for (int j = 0; j < 8; j++) {
#pragma unroll
                for (int e = 0; e < 2; e++) {
                    int cl = wn * 64 + j * 8 + (lane & 3) * 2 + e;
                    int v = col0 + cl;
                    float s = w2s[cl] - 2.0f * acc[i][j][h * 2 + e];
                    int ok = (v < VWORDS) & (v != t);
                    clo += ok & (s < stl);
                    chi += ok & (s <= sth);
                }
            }
            clo += __shfl_xor_sync(0xffffffffu, clo, 1);
            clo += __shfl_xor_sync(0xffffffffu, clo, 2);
            chi += __shfl_xor_sync(0xffffffffu, chi, 1);
            chi += __shfl_xor_sync(0xffffffffu, chi, 2);
            if ((lane & 3) == 0 && valid) {
                if (clo) atomicAdd(&slo[rloc], clo);
                if (chi) atomicAdd(&shi[rloc], chi);
            }
        }
    }
    __syncthreads();
    if (tid < TM) {
        int gi = row0 + tid;
        if (gi < nm) {
            if (slo[tid]) atomicAdd(&g_clo[gi], slo[tid]);
            if (shi[tid]) atomicAdd(&g_chi[gi], shi[tid]);
        }
    }
}

// ---------------------------------------------------------------------------
// K3: classify rows — certain hit / certain miss / ambiguous (builds g_amb)
__global__ void k_classify() {
    int i = blockIdx.x * blockDim.x + threadIdx.x;
    if (i >= g_nm) return;
    int clo = g_clo[i], chi = g_chi[i];
    if (clo >= KNN) return;                             // certain miss
    if (chi < KNN) { atomicAdd(&g_hits, 1); return; }   // certain hit
    int p = atomicAdd(&g_namb, 1);
    g_amb[p] = i;
}

// ---------------------------------------------------------------------------
// K4 (fused): exact f32 recount for ambiguous rows (early-exit via g_amb list)
//             + last-block final reduction (ticket pattern, small grid).
__global__ __launch_bounds__(256) void k_exact(const float* __restrict__ X,
                                               const float* __restrict__ W,
                                               float* __restrict__ out) {
    const int namb = g_namb;
    const int v0 = blockIdx.x * VCHUNK;
    const int v1 = min(v0 + VCHUNK, VWORDS);
    const int lane = threadIdx.x & 31;
    const int warp = threadIdx.x >> 5;

    for (int ai = blockIdx.y; ai < namb; ai += ASLOTS) {
        const int i = g_amb[ai];
        const int n = g_rowlist[i], t = g_tgt[i];
        const float st = g_st[i];
        const float4* xr = reinterpret_cast<const float4*>(X + (size_t)n * DIM);
        float4 x0 = xr[lane], x1 = xr[lane + 32], x2 = xr[lane + 64], x3 = xr[lane + 96];
        int cnt = 0;
        for (int v = v0 + warp; v < v1; v += 8) {
            const float4* wr = reinterpret_cast<const float4*>(W + (size_t)v * DIM);
            float4 w0 = wr[lane], w1 = wr[lane + 32], w2v = wr[lane + 64], w3 = wr[lane + 96];
            float p = x0.x * w0.x + x0.y * w0.y + x0.z * w0.z + x0.w * w0.w;
            p += x1.x * w1.x + x1.y * w1.y + x1.z * w1.z + x1.w * w1.w;
            p += x2.x * w2v.x + x2.y * w2v.y + x2.z * w2v.z + x2.w * w2v.w;
            p += x3.x * w3.x + x3.y * w3.y + x3.z * w3.z + x3.w * w3.w;
#pragma unroll
            for (int o = 16; o; o >>= 1) p += __shfl_down_sync(0xffffffffu, p, o);
            if (lane == 0 && v != t) {
                float s = g_w2[v] - 2.0f * p;
                cnt += (s < st) || (s == st && v < t);
            }
        }
        if (lane == 0 && cnt) atomicAdd(&g_exc[ai], cnt);
    }

    // ---- last-block finalize (scans only namb elements) ----
    __threadfence();
    __shared__ int isLast;
    if (threadIdx.x == 0) {
        int tk = atomicAdd(&g_done, 1);
        isLast = (tk == VSPLIT * ASLOTS - 1);
    }
    __syncthreads();
    if (!isLast) return;
    __threadfence();

    float s = 0.0f;
    for (int ai = threadIdx.x; ai < namb; ai += 256)
        s += (g_exc[ai] < KNN) ? 1.0f : 0.0f;
#pragma unroll
    for (int o = 16; o; o >>= 1) s += __shfl_down_sync(0xffffffffu, s, o);
    __shared__ float red[8];
    if ((threadIdx.x & 31) == 0) red[threadIdx.x >> 5] = s;
    __syncthreads();
    if (threadIdx.x == 0) {
        float tot = (float)g_hits;
#pragma unroll
        for (int i = 0; i < 8; i++) tot += red[i];
        int nm = g_nm;
        out[0] = (nm > 0) ? (tot / (float)nm) : 0.0f;
    }
}

// ---------------------------------------------------------------------------
extern "C" void kernel_launch(void* const* d_in, const int* in_sizes, int n_in,
                              void* d_out, int out_size) {
    const float*     logits = (const float*)d_in[0];
    const long long* target = (const long long*)d_in[1];
    const int*       mask   = (const int*)d_in[2];
    const float*     W      = (const float*)d_in[3];

    cudaFuncSetAttribute(k_mma, cudaFuncAttributeMaxDynamicSharedMemorySize, SM_TOTAL);

    k_prep<<<PREP_BLOCKS + N_ROWS, 256>>>(W, logits, target, mask);
    k_mma<<<dim3(RTILES, CTILES), 256, SM_TOTAL>>>();
    k_classify<<<(N_ROWS + 255) / 256, 256>>>();
    k_exact<<<dim3(VSPLIT, ASLOTS), 256>>>(logits, W, (float*)d_out);
}